// round 15
// baseline (speedup 1.0000x reference)
#include <cuda_runtime.h>
#include <cuda_fp16.h>
#include <cstdint>
#include <math.h>

// Problem constants
#define B_  32
#define T_  1536
#define C_  768
#define G_  2
#define VG_ 160
#define M_TOTAL (B_*T_)       // 49152
#define N1 (G_*VG_)           // 320
#define N2 C_                 // 768
#define TEMP_ 2.0f

#define GAP_THRESH  0.015f
#define CAND_WINDOW 0.025f

// ---- device scratch (allocation-free rule) ----
__device__ __half  g_probs16[(size_t)M_TOTAL * N1];
__device__ __half  g_Wt16   [(size_t)N1 * C_];   // [n][k]
__device__ __half  g_cbt16  [(size_t)C_ * N1];   // [c][v]
__device__ int     g_wl_count;
__device__ int     g_wl[M_TOTAL * G_];

// ---- PTX helpers ----
__device__ __forceinline__ void mma_f16(float c[4],
    uint32_t a0, uint32_t a1, uint32_t a2, uint32_t a3,
    uint32_t b0, uint32_t b1)
{
    asm volatile(
        "mma.sync.aligned.m16n8k16.row.col.f32.f16.f16.f32 "
        "{%0,%1,%2,%3}, {%4,%5,%6,%7}, {%8,%9}, {%0,%1,%2,%3};"
        : "+f"(c[0]), "+f"(c[1]), "+f"(c[2]), "+f"(c[3])
        : "r"(a0), "r"(a1), "r"(a2), "r"(a3), "r"(b0), "r"(b1));
}
__device__ __forceinline__ void ldsm4(uint32_t& r0, uint32_t& r1, uint32_t& r2, uint32_t& r3,
                                      uint32_t addr)
{
    asm volatile("ldmatrix.sync.aligned.m8n8.x4.shared.b16 {%0,%1,%2,%3}, [%4];"
                 : "=r"(r0), "=r"(r1), "=r"(r2), "=r"(r3) : "r"(addr));
}
__device__ __forceinline__ void ldsm2(uint32_t& r0, uint32_t& r1, uint32_t addr)
{
    asm volatile("ldmatrix.sync.aligned.m8n8.x2.shared.b16 {%0,%1}, [%2];"
                 : "=r"(r0), "=r"(r1) : "r"(addr));
}
__device__ __forceinline__ uint32_t s2u(const void* p){
    uint32_t a;
    asm("{ .reg .u64 t; cvta.to.shared.u64 t, %1; cvt.u32.u64 %0, t; }" : "=r"(a) : "l"(p));
    return a;
}

// =================== Fused GEMM1 + softmax + argmax ===================
// grid (2, 384): blockIdx.x = group g, blockIdx.y = 128-row block. 512 threads.
// Warp layout: 16 warps = 4 wm x 4 wn; warp tile 32 rows x 40 cols.
// Stage layout (bytes, per stage of 41472): A[128 rows x 144B], B 160 x 144B at +18432.
#define FS_STAGE 41472
#define FS_RED   82944        // reduction arrays start
#define FS_SMEM  (82944 + 4*128*4*3 + 128*4*4)   // stages + sB/sS/sI + gB/gSum/gI/gF = 91136

__global__ __launch_bounds__(512, 1)
void gemm1_softmax_fused(const float* __restrict__ x, const __half* __restrict__ Wt,
                         const float* __restrict__ bias, const float* __restrict__ gumbel,
                         float* __restrict__ probs_out, float* __restrict__ codes_out)
{
    extern __shared__ char sm[];
    const uint32_t base = s2u(sm);
    float* sB   = (float*)(sm + FS_RED);            // [4][128]
    float* sS   = sB + 4*128;                        // [4][128]
    int*   sI   = (int*)(sS + 4*128);                // [4][128]
    float* gB   = (float*)(sI + 4*128);              // [128]
    float* gSum = gB + 128;                          // [128]
    int*   gI   = (int*)(gSum + 128);                // [128]
    int*   gF   = gI + 128;                          // [128]

    const int tid  = threadIdx.x;
    const int warp = tid >> 5, lane = tid & 31;
    const int wm = warp >> 2, wn = warp & 3;
    const int g  = blockIdx.x;
    const int m0 = blockIdx.y * 128;
    const int n0 = g * VG_;                          // W row offset
    const int g4 = lane >> 2, t = lane & 3;

    const uint32_t aLane = (uint32_t)(lane & 15) * 144u + (uint32_t)(lane >> 4) * 16u;
    const uint32_t bLane = (uint32_t)((lane & 7) | ((lane >> 4) << 3)) * 144u
                         + (uint32_t)((lane >> 3) & 1) * 16u;

    float acc[2][5][4];
    #pragma unroll
    for (int mt = 0; mt < 2; mt++)
        #pragma unroll
        for (int nt = 0; nt < 5; nt++)
            #pragma unroll
            for (int r = 0; r < 4; r++) acc[mt][nt][r] = 0.0f;

    uint2 avp[4];
    uint4 bv[3];

    auto ldg = [&](int k0) {
        #pragma unroll
        for (int i = 0; i < 4; i++) {
            int idx = tid + i * 512, r = idx >> 4, c4 = idx & 15;
            float4 v = *(const float4*)(x + (size_t)(m0 + r) * C_ + k0 + c4 * 4);
            __half2 h01 = __floats2half2_rn(v.x, v.y);
            __half2 h23 = __floats2half2_rn(v.z, v.w);
            avp[i] = make_uint2(*(uint32_t*)&h01, *(uint32_t*)&h23);
        }
        #pragma unroll
        for (int i = 0; i < 3; i++) {
            int idx = tid + i * 512;
            if (idx < 1280) {
                int r = idx >> 3, ch = idx & 7;
                bv[i] = *(const uint4*)(Wt + (size_t)(n0 + r) * C_ + k0 + ch * 8);
            }
        }
    };
    auto sts = [&](int s) {
        char* st = sm + s * FS_STAGE;
        #pragma unroll
        for (int i = 0; i < 4; i++) {
            int idx = tid + i * 512, r = idx >> 4, c4 = idx & 15;
            *(uint2*)(st + r * 144 + c4 * 8) = avp[i];
        }
        #pragma unroll
        for (int i = 0; i < 3; i++) {
            int idx = tid + i * 512;
            if (idx < 1280) {
                int r = idx >> 3, ch = idx & 7;
                *(uint4*)(st + 18432 + r * 144 + ch * 16) = bv[i];
            }
        }
    };

    ldg(0);
    #pragma unroll 1
    for (int it = 0; it < C_ / 64; ++it) {
        sts(it & 1);
        if (it + 1 < C_ / 64) ldg((it + 1) * 64);
        __syncthreads();

        const uint32_t aBase = base + (uint32_t)(it & 1) * FS_STAGE + (uint32_t)(wm * 32) * 144u + aLane;
        const uint32_t bBase = base + (uint32_t)(it & 1) * FS_STAGE + 18432u + (uint32_t)(wn * 40) * 144u + bLane;
        #pragma unroll
        for (int ks = 0; ks < 4; ks++) {
            const uint32_t kOff = (uint32_t)ks * 32u;
            uint32_t a[2][4];
            ldsm4(a[0][0], a[0][1], a[0][2], a[0][3], aBase + kOff);
            ldsm4(a[1][0], a[1][1], a[1][2], a[1][3], aBase + 16u * 144u + kOff);
            uint32_t b0, b1, b2, b3;
            ldsm4(b0, b1, b2, b3, bBase + kOff);
            mma_f16(acc[0][0], a[0][0], a[0][1], a[0][2], a[0][3], b0, b1);
            mma_f16(acc[1][0], a[1][0], a[1][1], a[1][2], a[1][3], b0, b1);
            mma_f16(acc[0][1], a[0][0], a[0][1], a[0][2], a[0][3], b2, b3);
            mma_f16(acc[1][1], a[1][0], a[1][1], a[1][2], a[1][3], b2, b3);
            ldsm4(b0, b1, b2, b3, bBase + 16u * 144u + kOff);
            mma_f16(acc[0][2], a[0][0], a[0][1], a[0][2], a[0][3], b0, b1);
            mma_f16(acc[1][2], a[1][0], a[1][1], a[1][2], a[1][3], b0, b1);
            mma_f16(acc[0][3], a[0][0], a[0][1], a[0][2], a[0][3], b2, b3);
            mma_f16(acc[1][3], a[1][0], a[1][1], a[1][2], a[1][3], b2, b3);
            ldsm2(b0, b1, bBase + 32u * 144u + kOff);
            mma_f16(acc[0][4], a[0][0], a[0][1], a[0][2], a[0][3], b0, b1);
            mma_f16(acc[1][4], a[1][0], a[1][1], a[1][2], a[1][3], b0, b1);
        }
    }

    // ================= softmax epilogue =================
    // rows per thread: slot = mt*2+h -> row = wm*32 + mt*16 + h*8 + g4
    const int colb = wn * 40 + t * 2;               // within-group col base (+ nt*8)
    int rows[4];
    #pragma unroll
    for (int s = 0; s < 4; s++) rows[s] = wm * 32 + (s >> 1) * 16 + (s & 1) * 8 + g4;

    // z = acc + bias + gumbel (in place)
    float2 bs[5];
    #pragma unroll
    for (int nt = 0; nt < 5; nt++) bs[nt] = *(const float2*)(bias + g * VG_ + colb + nt * 8);
    #pragma unroll
    for (int mt = 0; mt < 2; mt++)
        #pragma unroll
        for (int h = 0; h < 2; h++) {
            const float* gu = gumbel + (size_t)(m0 + rows[mt*2+h]) * N1 + g * VG_ + colb;
            #pragma unroll
            for (int nt = 0; nt < 5; nt++) {
                float2 gv = *(const float2*)(gu + nt * 8);
                acc[mt][nt][h*2]   += bs[nt].x + gv.x;
                acc[mt][nt][h*2+1] += bs[nt].y + gv.y;
            }
        }

    // per-row (best, second, idx): local -> quad shfl -> smem per-wn
    #pragma unroll
    for (int s = 0; s < 4; s++) {
        const int mt = s >> 1, h = s & 1;
        float b = -INFINITY, sc = -INFINITY; int bi = 0;
        #pragma unroll
        for (int nt = 0; nt < 5; nt++) {
            float z0 = acc[mt][nt][h*2], z1 = acc[mt][nt][h*2+1];
            int c0 = colb + nt * 8;
            if (z0 > b) { sc = b; b = z0; bi = c0; } else if (z0 > sc) sc = z0;
            if (z1 > b) { sc = b; b = z1; bi = c0 + 1; } else if (z1 > sc) sc = z1;
        }
        #pragma unroll
        for (int o = 1; o <= 2; o <<= 1) {
            float ov = __shfl_xor_sync(0xffffffffu, b,  o);
            float os = __shfl_xor_sync(0xffffffffu, sc, o);
            int   oi = __shfl_xor_sync(0xffffffffu, bi, o);
            if (ov > b || (ov == b && oi < bi)) { sc = fmaxf(b, os); b = ov; bi = oi; }
            else                                 { sc = fmaxf(sc, ov); }
        }
        if (t == 0) {
            sB[wn * 128 + rows[s]] = b;
            sS[wn * 128 + rows[s]] = sc;
            sI[wn * 128 + rows[s]] = bi;
        }
    }
    __syncthreads();

    if (tid < 128) {
        float b = -INFINITY, sc = -INFINITY; int bi = 0;
        #pragma unroll
        for (int w = 0; w < 4; w++) {
            float ov = sB[w * 128 + tid], os = sS[w * 128 + tid];
            int   oi = sI[w * 128 + tid];
            if (ov > b || (ov == b && oi < bi)) { sc = fmaxf(b, os); b = ov; bi = oi; }
            else                                 { sc = fmaxf(sc, ov); }
        }
        gB[tid] = b; gI[tid] = bi;
        gF[tid] = (b - sc < GAP_THRESH) ? 1 : 0;
        gSum[tid] = 0.0f;
    }
    __syncthreads();

    // exp (in place) + row sums
    #pragma unroll
    for (int s = 0; s < 4; s++) {
        const int mt = s >> 1, h = s & 1;
        const float m = gB[rows[s]];
        float se = 0.0f;
        #pragma unroll
        for (int nt = 0; nt < 5; nt++) {
            float e0 = __expf((acc[mt][nt][h*2]   - m) * (1.0f / TEMP_));
            float e1 = __expf((acc[mt][nt][h*2+1] - m) * (1.0f / TEMP_));
            acc[mt][nt][h*2] = e0; acc[mt][nt][h*2+1] = e1;
            se += e0 + e1;
        }
        se += __shfl_xor_sync(0xffffffffu, se, 1);
        se += __shfl_xor_sync(0xffffffffu, se, 2);
        if (t == 0) atomicAdd(&gSum[rows[s]], se);
    }
    __syncthreads();

    // write probs (fp32 output + fp16 for GEMM2)
    #pragma unroll
    for (int s = 0; s < 4; s++) {
        const int mt = s >> 1, h = s & 1;
        const int grow = m0 + rows[s];
        const float inv = 1.0f / gSum[rows[s]];
        float*  po = probs_out + (size_t)grow * N1 + g * VG_ + colb;
        __half* ph = g_probs16 + (size_t)grow * N1 + g * VG_ + colb;
        #pragma unroll
        for (int nt = 0; nt < 5; nt++) {
            float p0 = acc[mt][nt][h*2] * inv, p1 = acc[mt][nt][h*2+1] * inv;
            *(float2*)(po + nt * 8) = make_float2(p0, p1);
            *(__half2*)(ph + nt * 8) = __floats2half2_rn(p0, p1);
        }
    }

    // codes / worklist
    if (tid < 128) {
        int task = (m0 + tid) * G_ + g;
        if (gF[tid]) { int p = atomicAdd(&g_wl_count, 1); g_wl[p] = task; }
        else codes_out[task] = (float)gI[tid];
    }
}

// =================== rescue: exact argmax for flagged rows ===================
__global__ void reset_counter() { if (threadIdx.x == 0) g_wl_count = 0; }

__global__ __launch_bounds__(256)
void rescue_kernel(const float* __restrict__ x, const float* __restrict__ W,
                   const float* __restrict__ bias, const float* __restrict__ gumbel,
                   float* __restrict__ codes_out)
{
    const int gw = (blockIdx.x * 256 + threadIdx.x) >> 5;
    const int lane = threadIdx.x & 31;
    const int nw = gridDim.x * 8;
    const int cnt = g_wl_count;

    for (int e = gw; e < cnt; e += nw) {
        const int task = g_wl[e];
        const int row = task >> 1, g = task & 1;
        const float* xr = x + (size_t)row * C_;

        // fp32 recompute of this row's 160 logits (5 cols per lane)
        float zv[5];
        {
            float a0 = 0, a1 = 0, a2 = 0, a3 = 0, a4 = 0;
            const float* wp = W + g * VG_ + lane;
            for (int k = 0; k < C_; k++) {
                float xk = xr[k];
                const float* wr = wp + (size_t)k * N1;
                a0 += xk * wr[0];   a1 += xk * wr[32];  a2 += xk * wr[64];
                a3 += xk * wr[96];  a4 += xk * wr[128];
            }
            zv[0]=a0; zv[1]=a1; zv[2]=a2; zv[3]=a3; zv[4]=a4;
            #pragma unroll
            for (int j = 0; j < 5; j++) {
                int col = g * VG_ + lane + j * 32;
                zv[j] += bias[col] + gumbel[(size_t)row * N1 + col];
            }
        }
        // approx warp max
        float best = -INFINITY;
        #pragma unroll
        for (int j = 0; j < 5; j++) best = fmaxf(best, zv[j]);
        #pragma unroll
        for (int o = 16; o > 0; o >>= 1) best = fmaxf(best, __shfl_xor_sync(0xffffffffu, best, o));

        // fp64 refinement of candidates within window
        double nbest = -1e300; int nidx = 0;
        #pragma unroll
        for (int j = 0; j < 5; j++) {
            unsigned m = __ballot_sync(0xffffffffu, zv[j] > best - CAND_WINDOW);
            while (m) {
                int l = __ffs(m) - 1; m &= m - 1;
                int v = l + j * 32;
                int col = g * VG_ + v;
                double part = 0.0;
                for (int k = lane; k < C_; k += 32)
                    part += (double)xr[k] * (double)W[(size_t)k * N1 + col];
                #pragma unroll
                for (int o = 16; o > 0; o >>= 1)
                    part += __shfl_xor_sync(0xffffffffu, part, o);
                double ze = part + (double)bias[col] + (double)gumbel[(size_t)row * N1 + col];
                if (ze > nbest) { nbest = ze; nidx = v; }   // ascending v -> first max kept
            }
        }
        if (lane == 0) codes_out[task] = (float)nidx;
    }
}

// =================== GEMM2 (round-12 proven config) ===================
#define BK 64
#define P32 36
#define SA (128*P32)
#define SB (64*P32)
#define SS (SA+SB)
#define SMEM_G (2*SS*4)

__global__ __launch_bounds__(256, 2)
void gemm2_f16(const __half* __restrict__ A16, const __half* __restrict__ Bg,
               float* __restrict__ Out)
{
    extern __shared__ uint32_t sm32[];
    uint32_t* aS[2] = { sm32,       sm32 + SS };
    uint32_t* bS[2] = { sm32 + SA,  sm32 + SS + SA };
    const uint32_t smemB = s2u(sm32);
    const uint32_t aByte[2] = { smemB,          smemB + SS * 4 };
    const uint32_t bByte[2] = { smemB + SA * 4, smemB + (SS + SA) * 4 };

    const int tid  = threadIdx.x;
    const int warp = tid >> 5, lane = tid & 31;
    const int wm = warp >> 1, wn = warp & 1;
    const int m0 = blockIdx.y * 128, n0 = blockIdx.x * 64;
    const int g = lane >> 2, t = lane & 3;

    const uint32_t aLane = (uint32_t)(lane & 15) * 144u + (uint32_t)(lane >> 4) * 16u;
    const uint32_t bLane = (uint32_t)((lane & 7) | ((lane >> 4) << 3)) * 144u
                         + (uint32_t)((lane >> 3) & 1) * 16u;

    float acc[2][4][4];
    #pragma unroll
    for (int mt = 0; mt < 2; mt++)
        #pragma unroll
        for (int nt = 0; nt < 4; nt++)
            #pragma unroll
            for (int r = 0; r < 4; r++) acc[mt][nt][r] = 0.0f;

    uint4 avh[4];
    uint4 bv[2];

    auto ldg = [&](int k0) {
        #pragma unroll
        for (int i = 0; i < 4; i++) {
            int idx = tid + i * 256, r = idx >> 3, ch = idx & 7;
            avh[i] = *(const uint4*)(A16 + (size_t)(m0 + r) * N1 + k0 + ch * 8);
        }
        #pragma unroll
        for (int i = 0; i < 2; i++) {
            int idx = tid + i * 256, r = idx >> 3, ch = idx & 7;
            bv[i] = *(const uint4*)(Bg + (size_t)(n0 + r) * N1 + k0 + ch * 8);
        }
    };
    auto sts = [&](int s) {
        #pragma unroll
        for (int i = 0; i < 4; i++) {
            int idx = tid + i * 256, r = idx >> 3, ch = idx & 7;
            *(uint4*)(aS[s] + r * P32 + ch * 4) = avh[i];
        }
        #pragma unroll
        for (int i = 0; i < 2; i++) {
            int idx = tid + i * 256, r = idx >> 3, ch = idx & 7;
            *(uint4*)(bS[s] + r * P32 + ch * 4) = bv[i];
        }
    };

    ldg(0);
    #pragma unroll 1
    for (int it = 0; it < N1 / BK; ++it) {
        sts(it & 1);
        if (it + 1 < N1 / BK) ldg((it + 1) * BK);
        __syncthreads();

        const uint32_t aBase = aByte[it & 1] + (uint32_t)(wm * 32) * 144u + aLane;
        const uint32_t bBase = bByte[it & 1] + (uint32_t)(wn * 32) * 144u + bLane;
        #pragma unroll
        for (int ks = 0; ks < 4; ks++) {
            const uint32_t kOff = (uint32_t)ks * 32u;
            uint32_t a[2][4];
            ldsm4(a[0][0], a[0][1], a[0][2], a[0][3], aBase + kOff);
            ldsm4(a[1][0], a[1][1], a[1][2], a[1][3], aBase + 16u * 144u + kOff);
            #pragma unroll
            for (int p = 0; p < 2; p++) {
                uint32_t b00, b01, b10, b11;
                ldsm4(b00, b01, b10, b11, bBase + (uint32_t)(p * 16) * 144u + kOff);
                mma_f16(acc[0][p*2  ], a[0][0], a[0][1], a[0][2], a[0][3], b00, b01);
                mma_f16(acc[1][p*2  ], a[1][0], a[1][1], a[1][2], a[1][3], b00, b01);
                mma_f16(acc[0][p*2+1], a[0][0], a[0][1], a[0][2], a[0][3], b10, b11);
                mma_f16(acc[1][p*2+1], a[1][0], a[1][1], a[1][2], a[1][3], b10, b11);
            }
        }
    }

    #pragma unroll
    for (int mt = 0; mt < 2; mt++) {
        #pragma unroll
        for (int nt = 0; nt < 4; nt++) {
            int row0 = m0 + wm * 32 + mt * 16 + g;
            int col0 = n0 + wn * 32 + nt * 8 + t * 2;
            *(float2*)(Out + (size_t)(row0    ) * N2 + col0) = make_float2(acc[mt][nt][0], acc[mt][nt][1]);
            *(float2*)(Out + (size_t)(row0 + 8) * N2 + col0) = make_float2(acc[mt][nt][2], acc[mt][nt][3]);
        }
    }
}

// ---------------- prep: transpose + fp16 convert of W and codebook ----------------
__global__ void prep_both(const float* __restrict__ W, const float* __restrict__ cb) {
    int i = blockIdx.x * 256 + threadIdx.x;
    if (i < N1 * C_) {
        int n = i / C_, k = i % C_;
        g_Wt16[i] = __float2half_rn(W[(size_t)k * N1 + n]);
    }
    int j = i - N1 * C_;
    if (j >= 0 && j < C_ * N1) {
        int c = j / N1, v = j % N1;
        g_cbt16[j] = __float2half_rn(cb[(size_t)v * C_ + c]);
    }
}

// ---------------- launch ----------------
extern "C" void kernel_launch(void* const* d_in, const int* in_sizes, int n_in,
                              void* d_out, int out_size)
{
    const float* x      = (const float*)d_in[0];  // (B,T,C)
    const float* gumbel = (const float*)d_in[1];  // (B,T,G,Vg)
    const float* W      = (const float*)d_in[2];  // (C, G*Vg)
    const float* bias   = (const float*)d_in[3];  // (G*Vg,)
    const float* cb     = (const float*)d_in[4];  // (G,Vg,C) -> (320,768)

    float* out   = (float*)d_out;
    float* quant = out;                                      // M*C
    float* codes = out + (size_t)M_TOTAL * C_;               // M*G
    float* probs = codes + (size_t)M_TOTAL * G_;             // M*N1

    static __half *wt16, *cbt16, *pr16;
    static bool init_done = false;
    if (!init_done) {
        cudaGetSymbolAddress((void**)&wt16,  g_Wt16);
        cudaGetSymbolAddress((void**)&cbt16, g_cbt16);
        cudaGetSymbolAddress((void**)&pr16,  g_probs16);
        cudaFuncSetAttribute((const void*)gemm1_softmax_fused,
                             cudaFuncAttributeMaxDynamicSharedMemorySize, FS_SMEM);
        cudaFuncSetAttribute((const void*)gemm2_f16,
                             cudaFuncAttributeMaxDynamicSharedMemorySize, SMEM_G);
        init_done = true;
    }

    reset_counter<<<1, 32>>>();
    prep_both<<<(2 * N1 * C_ + 255) / 256, 256>>>(W, cb);

    // GEMM1 + softmax + argmax fused
    gemm1_softmax_fused<<<dim3(G_, M_TOTAL / 128), 512, FS_SMEM>>>(
        x, wt16, bias, gumbel, probs, codes);

    // exact rescue for flagged rows (fixed grid, strided over worklist)
    rescue_kernel<<<256, 256>>>(x, W, bias, gumbel, codes);

    // GEMM2: quantized = probs @ codebook
    gemm2_f16<<<dim3(N2 / 64, M_TOTAL / 128), 256, SMEM_G>>>(pr16, cbt16, quant);
}

// round 17
// speedup vs baseline: 1.5780x; 1.5780x over previous
#include <cuda_runtime.h>
#include <cuda_fp16.h>
#include <cstdint>
#include <math.h>

// Problem constants
#define B_  32
#define T_  1536
#define C_  768
#define G_  2
#define VG_ 160
#define M_TOTAL (B_*T_)       // 49152
#define N1 (G_*VG_)           // 320
#define N2 C_                 // 768
#define TEMP_ 2.0f

// ---- device scratch (allocation-free rule) ----
__device__ float   g_logits [(size_t)M_TOTAL * N1];
__device__ __half  g_probs16[(size_t)M_TOTAL * N1];
__device__ __half  g_Wt16   [(size_t)N1 * C_];   // [n][k]
__device__ __half  g_cbt16  [(size_t)C_ * N1];   // [c][v]

// ---- PTX helpers ----
__device__ __forceinline__ void mma_f16(float c[4],
    uint32_t a0, uint32_t a1, uint32_t a2, uint32_t a3,
    uint32_t b0, uint32_t b1)
{
    asm volatile(
        "mma.sync.aligned.m16n8k16.row.col.f32.f16.f16.f32 "
        "{%0,%1,%2,%3}, {%4,%5,%6,%7}, {%8,%9}, {%0,%1,%2,%3};"
        : "+f"(c[0]), "+f"(c[1]), "+f"(c[2]), "+f"(c[3])
        : "r"(a0), "r"(a1), "r"(a2), "r"(a3), "r"(b0), "r"(b1));
}
__device__ __forceinline__ void ldsm4(uint32_t& r0, uint32_t& r1, uint32_t& r2, uint32_t& r3,
                                      uint32_t addr)
{
    asm volatile("ldmatrix.sync.aligned.m8n8.x4.shared.b16 {%0,%1,%2,%3}, [%4];"
                 : "=r"(r0), "=r"(r1), "=r"(r2), "=r"(r3) : "r"(addr));
}
__device__ __forceinline__ uint32_t s2u(const void* p){
    uint32_t a;
    asm("{ .reg .u64 t; cvta.to.shared.u64 t, %1; cvt.u32.u64 %0, t; }" : "=r"(a) : "l"(p));
    return a;
}

// =================== GEMM1 (round-12 proven): 128x64 tiles ===================
#define BK 64
#define P32 36                // b32 pitch per row (144B)
#define SA (128*P32)
#define SB (64*P32)
#define SS (SA+SB)
#define SMEM_G (2*SS*4)       // 55296

__global__ __launch_bounds__(256, 2)
void gemm1_f16(const float* __restrict__ A32, const __half* __restrict__ Bg,
               const float* __restrict__ bias, float* __restrict__ Out)
{
    extern __shared__ uint32_t sm32[];
    uint32_t* aS[2] = { sm32,       sm32 + SS };
    uint32_t* bS[2] = { sm32 + SA,  sm32 + SS + SA };
    const uint32_t smemB = s2u(sm32);
    const uint32_t aByte[2] = { smemB,          smemB + SS * 4 };
    const uint32_t bByte[2] = { smemB + SA * 4, smemB + (SS + SA) * 4 };

    const int tid  = threadIdx.x;
    const int warp = tid >> 5, lane = tid & 31;
    const int wm = warp >> 1, wn = warp & 1;
    const int m0 = blockIdx.y * 128, n0 = blockIdx.x * 64;
    const int g = lane >> 2, t = lane & 3;

    const uint32_t aLane = (uint32_t)(lane & 15) * 144u + (uint32_t)(lane >> 4) * 16u;
    const uint32_t bLane = (uint32_t)((lane & 7) | ((lane >> 4) << 3)) * 144u
                         + (uint32_t)((lane >> 3) & 1) * 16u;

    float acc[2][4][4];
    #pragma unroll
    for (int mt = 0; mt < 2; mt++)
        #pragma unroll
        for (int nt = 0; nt < 4; nt++)
            #pragma unroll
            for (int r = 0; r < 4; r++) acc[mt][nt][r] = 0.0f;

    uint2 avp[8];
    uint4 bv[2];

    auto ldg = [&](int k0) {
        #pragma unroll
        for (int i = 0; i < 8; i++) {
            int idx = tid + i * 256, r = idx >> 4, c4 = idx & 15;
            float4 v = *(const float4*)(A32 + (size_t)(m0 + r) * C_ + k0 + c4 * 4);
            __half2 h01 = __floats2half2_rn(v.x, v.y);
            __half2 h23 = __floats2half2_rn(v.z, v.w);
            avp[i] = make_uint2(*(uint32_t*)&h01, *(uint32_t*)&h23);
        }
        #pragma unroll
        for (int i = 0; i < 2; i++) {
            int idx = tid + i * 256, r = idx >> 3, ch = idx & 7;
            bv[i] = *(const uint4*)(Bg + (size_t)(n0 + r) * C_ + k0 + ch * 8);
        }
    };
    auto sts = [&](int s) {
        #pragma unroll
        for (int i = 0; i < 8; i++) {
            int idx = tid + i * 256, r = idx >> 4, c4 = idx & 15;
            *(uint2*)(aS[s] + r * P32 + c4 * 2) = avp[i];
        }
        #pragma unroll
        for (int i = 0; i < 2; i++) {
            int idx = tid + i * 256, r = idx >> 3, ch = idx & 7;
            *(uint4*)(bS[s] + r * P32 + ch * 4) = bv[i];
        }
    };

    ldg(0);
    #pragma unroll 1
    for (int it = 0; it < C_ / BK; ++it) {
        sts(it & 1);
        if (it + 1 < C_ / BK) ldg((it + 1) * BK);
        __syncthreads();

        const uint32_t aBase = aByte[it & 1] + (uint32_t)(wm * 32) * 144u + aLane;
        const uint32_t bBase = bByte[it & 1] + (uint32_t)(wn * 32) * 144u + bLane;
        #pragma unroll
        for (int ks = 0; ks < 4; ks++) {
            const uint32_t kOff = (uint32_t)ks * 32u;
            uint32_t a[2][4];
            ldsm4(a[0][0], a[0][1], a[0][2], a[0][3], aBase + kOff);
            ldsm4(a[1][0], a[1][1], a[1][2], a[1][3], aBase + 16u * 144u + kOff);
            #pragma unroll
            for (int p = 0; p < 2; p++) {
                uint32_t b00, b01, b10, b11;
                ldsm4(b00, b01, b10, b11, bBase + (uint32_t)(p * 16) * 144u + kOff);
                mma_f16(acc[0][p*2  ], a[0][0], a[0][1], a[0][2], a[0][3], b00, b01);
                mma_f16(acc[1][p*2  ], a[1][0], a[1][1], a[1][2], a[1][3], b00, b01);
                mma_f16(acc[0][p*2+1], a[0][0], a[0][1], a[0][2], a[0][3], b10, b11);
                mma_f16(acc[1][p*2+1], a[1][0], a[1][1], a[1][2], a[1][3], b10, b11);
            }
        }
    }

    #pragma unroll
    for (int mt = 0; mt < 2; mt++) {
        #pragma unroll
        for (int nt = 0; nt < 4; nt++) {
            int row0 = m0 + wm * 32 + mt * 16 + g;
            int col0 = n0 + wn * 32 + nt * 8 + t * 2;
            float bv0 = bias[col0], bv1 = bias[col0 + 1];
            *(float2*)(Out + (size_t)(row0    ) * N1 + col0) =
                make_float2(acc[mt][nt][0] + bv0, acc[mt][nt][1] + bv1);
            *(float2*)(Out + (size_t)(row0 + 8) * N1 + col0) =
                make_float2(acc[mt][nt][2] + bv0, acc[mt][nt][3] + bv1);
        }
    }
}

// =================== GEMM2 (NEW): 128x128 CTA tile, warp tile 32x64 ===================
#define SA2 (128*P32)          // 4608 b32
#define SB2 (128*P32)          // 4608 b32
#define SS2 (SA2+SB2)          // 9216
#define SMEM_G2 (2*SS2*4)      // 73728

__global__ __launch_bounds__(256, 2)
void gemm2_wide(const __half* __restrict__ A16, const __half* __restrict__ Bg,
                float* __restrict__ Out)
{
    extern __shared__ uint32_t sm32[];
    uint32_t* aS[2] = { sm32,        sm32 + SS2 };
    uint32_t* bS[2] = { sm32 + SA2,  sm32 + SS2 + SA2 };
    const uint32_t smemB = s2u(sm32);
    const uint32_t aByte[2] = { smemB,           smemB + SS2 * 4 };
    const uint32_t bByte[2] = { smemB + SA2 * 4, smemB + (SS2 + SA2) * 4 };

    const int tid  = threadIdx.x;
    const int warp = tid >> 5, lane = tid & 31;
    const int wm = warp >> 1, wn = warp & 1;     // 4x2 warps -> 32x64 warp tiles
    const int m0 = blockIdx.y * 128, n0 = blockIdx.x * 128;
    const int g = lane >> 2, t = lane & 3;

    const uint32_t aLane = (uint32_t)(lane & 15) * 144u + (uint32_t)(lane >> 4) * 16u;
    const uint32_t bLane = (uint32_t)((lane & 7) | ((lane >> 4) << 3)) * 144u
                         + (uint32_t)((lane >> 3) & 1) * 16u;

    float acc[2][8][4];
    #pragma unroll
    for (int mt = 0; mt < 2; mt++)
        #pragma unroll
        for (int nt = 0; nt < 8; nt++)
            #pragma unroll
            for (int r = 0; r < 4; r++) acc[mt][nt][r] = 0.0f;

    uint4 avh[4], bv[4];

    auto ldg = [&](int k0) {
        #pragma unroll
        for (int i = 0; i < 4; i++) {
            int idx = tid + i * 256, r = idx >> 3, ch = idx & 7;
            avh[i] = *(const uint4*)(A16 + (size_t)(m0 + r) * N1 + k0 + ch * 8);
            bv[i]  = *(const uint4*)(Bg  + (size_t)(n0 + r) * N1 + k0 + ch * 8);
        }
    };
    auto sts = [&](int s) {
        #pragma unroll
        for (int i = 0; i < 4; i++) {
            int idx = tid + i * 256, r = idx >> 3, ch = idx & 7;
            *(uint4*)(aS[s] + r * P32 + ch * 4) = avh[i];
            *(uint4*)(bS[s] + r * P32 + ch * 4) = bv[i];
        }
    };

    ldg(0);
    #pragma unroll 1
    for (int it = 0; it < N1 / BK; ++it) {
        sts(it & 1);
        if (it + 1 < N1 / BK) ldg((it + 1) * BK);
        __syncthreads();

        const uint32_t aBase = aByte[it & 1] + (uint32_t)(wm * 32) * 144u + aLane;
        const uint32_t bBase = bByte[it & 1] + (uint32_t)(wn * 64) * 144u + bLane;
        #pragma unroll
        for (int ks = 0; ks < 4; ks++) {
            const uint32_t kOff = (uint32_t)ks * 32u;
            uint32_t a[2][4];
            ldsm4(a[0][0], a[0][1], a[0][2], a[0][3], aBase + kOff);
            ldsm4(a[1][0], a[1][1], a[1][2], a[1][3], aBase + 16u * 144u + kOff);
            #pragma unroll
            for (int p = 0; p < 4; p++) {
                uint32_t b00, b01, b10, b11;
                ldsm4(b00, b01, b10, b11, bBase + (uint32_t)(p * 16) * 144u + kOff);
                mma_f16(acc[0][p*2  ], a[0][0], a[0][1], a[0][2], a[0][3], b00, b01);
                mma_f16(acc[1][p*2  ], a[1][0], a[1][1], a[1][2], a[1][3], b00, b01);
                mma_f16(acc[0][p*2+1], a[0][0], a[0][1], a[0][2], a[0][3], b10, b11);
                mma_f16(acc[1][p*2+1], a[1][0], a[1][1], a[1][2], a[1][3], b10, b11);
            }
        }
    }

    #pragma unroll
    for (int mt = 0; mt < 2; mt++) {
        #pragma unroll
        for (int nt = 0; nt < 8; nt++) {
            int row0 = m0 + wm * 32 + mt * 16 + g;
            int col0 = n0 + wn * 64 + nt * 8 + t * 2;
            *(float2*)(Out + (size_t)(row0    ) * N2 + col0) = make_float2(acc[mt][nt][0], acc[mt][nt][1]);
            *(float2*)(Out + (size_t)(row0 + 8) * N2 + col0) = make_float2(acc[mt][nt][2], acc[mt][nt][3]);
        }
    }
}

// ---------------- prep: transpose + fp16 convert of W and codebook ----------------
__global__ void prep_both(const float* __restrict__ W, const float* __restrict__ cb) {
    int i = blockIdx.x * 256 + threadIdx.x;
    if (i < N1 * C_) {
        int n = i / C_, k = i % C_;
        g_Wt16[i] = __float2half_rn(W[(size_t)k * N1 + n]);
    }
    int j = i - N1 * C_;
    if (j >= 0 && j < C_ * N1) {
        int c = j / N1, v = j % N1;
        g_cbt16[j] = __float2half_rn(cb[(size_t)v * C_ + c]);
    }
}

// -------- Softmax + argmax (+ exact fp64 rescue, inline — round-12 proven) --------
#define GAP_THRESH  0.015f
#define CAND_WINDOW 0.025f

__global__ void softmax_argmax_kernel(const float* __restrict__ gumbel,
                                      const float* __restrict__ x,
                                      const float* __restrict__ W,
                                      const float* __restrict__ bias,
                                      float* __restrict__ probs_out,
                                      float* __restrict__ codes_out)
{
    const int task = blockIdx.x * 8 + (threadIdx.x >> 5);   // 98304 tasks
    const int lane = threadIdx.x & 31;
    const int row = task >> 1, g = task & 1;

    const float* lp = g_logits + (size_t)row * N1 + g * VG_;
    const float* gp = gumbel   + (size_t)row * N1 + g * VG_;

    float z[5];
    float best = -INFINITY, second = -INFINITY;
    int bidx = 0;
    #pragma unroll
    for (int j = 0; j < 5; j++) {
        int v = lane + j * 32;
        z[j] = lp[v] + gp[v];
        if (z[j] > best) { second = best; best = z[j]; bidx = v; }
        else if (z[j] > second) { second = z[j]; }
    }
    #pragma unroll
    for (int o = 16; o > 0; o >>= 1) {
        float ov = __shfl_xor_sync(0xffffffffu, best,   o);
        float os = __shfl_xor_sync(0xffffffffu, second, o);
        int   oi = __shfl_xor_sync(0xffffffffu, bidx,   o);
        if (ov > best || (ov == best && oi < bidx)) {
            second = fmaxf(best, os);
            best = ov; bidx = oi;
        } else {
            second = fmaxf(second, ov);
        }
    }

    if (best - second < GAP_THRESH) {
        double nbest = -1e300;
        int nidx = 0;
        #pragma unroll
        for (int j = 0; j < 5; j++) {
            unsigned m = __ballot_sync(0xffffffffu, z[j] > best - CAND_WINDOW);
            while (m) {
                int l = __ffs(m) - 1; m &= m - 1;
                int v = l + j * 32;
                int col = g * VG_ + v;
                double part = 0.0;
                const float* xr = x + (size_t)row * C_;
                for (int k = lane; k < C_; k += 32)
                    part += (double)xr[k] * (double)W[(size_t)k * N1 + col];
                #pragma unroll
                for (int o = 16; o > 0; o >>= 1)
                    part += __shfl_xor_sync(0xffffffffu, part, o);
                double ze = part + (double)bias[col] + (double)gp[v];
                if (ze > nbest) { nbest = ze; nidx = v; }  // v ascending -> first max kept
            }
        }
        bidx = nidx;
    }

    const float inv_t = 1.0f / TEMP_;
    float e[5];
    float s = 0.0f;
    #pragma unroll
    for (int j = 0; j < 5; j++) { e[j] = __expf((z[j] - best) * inv_t); s += e[j]; }
    #pragma unroll
    for (int o = 16; o > 0; o >>= 1) s += __shfl_xor_sync(0xffffffffu, s, o);
    float inv_s = 1.0f / s;

    float* po = probs_out + (size_t)row * N1 + g * VG_;
    __half* ph = g_probs16 + (size_t)row * N1 + g * VG_;
    #pragma unroll
    for (int j = 0; j < 5; j++) {
        int v = lane + j * 32;
        float p = e[j] * inv_s;
        po[v] = p;
        ph[v] = __float2half_rn(p);
    }

    if (lane == 0) codes_out[task] = (float)bidx;
}

// ---------------- launch ----------------
extern "C" void kernel_launch(void* const* d_in, const int* in_sizes, int n_in,
                              void* d_out, int out_size)
{
    const float* x      = (const float*)d_in[0];  // (B,T,C)
    const float* gumbel = (const float*)d_in[1];  // (B,T,G,Vg)
    const float* W      = (const float*)d_in[2];  // (C, G*Vg)
    const float* bias   = (const float*)d_in[3];  // (G*Vg,)
    const float* cb     = (const float*)d_in[4];  // (G,Vg,C) -> (320,768)

    float* out   = (float*)d_out;
    float* quant = out;                                      // M*C
    float* codes = out + (size_t)M_TOTAL * C_;               // M*G
    float* probs = codes + (size_t)M_TOTAL * G_;             // M*N1

    static float* logits_ptr = nullptr;
    static __half *wt16, *cbt16, *pr16;
    static bool init_done = false;
    if (!init_done) {
        cudaGetSymbolAddress((void**)&logits_ptr, g_logits);
        cudaGetSymbolAddress((void**)&wt16,  g_Wt16);
        cudaGetSymbolAddress((void**)&cbt16, g_cbt16);
        cudaGetSymbolAddress((void**)&pr16,  g_probs16);
        cudaFuncSetAttribute((const void*)gemm1_f16,
                             cudaFuncAttributeMaxDynamicSharedMemorySize, SMEM_G);
        cudaFuncSetAttribute((const void*)gemm2_wide,
                             cudaFuncAttributeMaxDynamicSharedMemorySize, SMEM_G2);
        init_done = true;
    }

    // prep: W^T and cb^T fp16 (single launch)
    prep_both<<<(2 * N1 * C_ + 255) / 256, 256>>>(W, cb);

    // GEMM1: logits = x @ W + b   (M x 768) @ (768 x 320)
    gemm1_f16<<<dim3(N1 / 64, M_TOTAL / 128), 256, SMEM_G>>>(x, wt16, bias, logits_ptr);

    // Softmax + argmax (+ inline exact rescue); emits probs fp32 + fp16
    softmax_argmax_kernel<<<(M_TOTAL * G_) / 8, 256>>>(gumbel, x, W, bias, probs, codes);

    // GEMM2: quantized = probs @ codebook   (M x 320) @ (320 x 768), 128x128 tiles
    gemm2_wide<<<dim3(N2 / 128, M_TOTAL / 128), 256, SMEM_G2>>>(pr16, cbt16, quant);
}